// round 9
// baseline (speedup 1.0000x reference)
#include <cuda_runtime.h>
#include <math.h>
#include <stdint.h>

#define N_NODES 4096
#define F_IN    256
#define C_TOT   256
#define HEADS   4
#define F_OUT   64
#define JSPLIT  4
#define NWORDS  (N_NODES / 32)
#define JTILE   64
#define JPER    (N_NODES / JSPLIT)
#define HSTR    72

__device__ float    g_h [N_NODES * C_TOT];
__device__ float    g_P1[N_NODES * HEADS];
__device__ float    g_P2[N_NODES * HEADS];
__device__ float    g_Q1[N_NODES * HEADS];
__device__ float    g_Q2[N_NODES * HEADS];
__device__ unsigned g_adjm[N_NODES * NWORDS];
__device__ float    g_part[JSPLIT * HEADS * N_NODES * F_OUT];
__device__ float    g_pden[JSPLIT * HEADS * N_NODES];

// ---------------------------------------------------------------------------
// K1: h = x @ W   (32x64 tiles -> 512 CTAs for wave balance)
//  As stride = 20 floats (80 B = 5x16 B) so float4 stores stay 16B-aligned.
// ---------------------------------------------------------------------------
__global__ __launch_bounds__(256) void k_gemm(const float* __restrict__ x,
                                              const float* __restrict__ W) {
    __shared__ __align__(16) float As[32][20];   // [m][k], aligned padding
    __shared__ __align__(16) float Bs[16][64];   // [k][n]
    const int t  = threadIdx.x;
    const int n0 = blockIdx.x * 64;
    const int m0 = blockIdx.y * 32;
    const int tx = t & 15, ty = t >> 4;          // ty: 2 rows, tx: 4 cols

    float acc[2][4];
#pragma unroll
    for (int i = 0; i < 2; ++i)
#pragma unroll
        for (int j = 0; j < 4; ++j) acc[i][j] = 0.f;

    for (int k0 = 0; k0 < F_IN; k0 += 16) {
        if (t < 128) {
            int row = t >> 2, k4 = (t & 3) * 4;
            *(float4*)&As[row][k4] = *(const float4*)&x[(m0 + row) * F_IN + k0 + k4];
        }
        {
            int krow = t >> 4, n4 = (t & 15) * 4;
            *(float4*)&Bs[krow][n4] = *(const float4*)&W[(k0 + krow) * C_TOT + n0 + n4];
        }
        __syncthreads();
#pragma unroll
        for (int kk = 0; kk < 16; ++kk) {
            float a0 = As[ty * 2][kk];
            float a1 = As[ty * 2 + 1][kk];
            float4 b = *(const float4*)&Bs[kk][tx * 4];
            acc[0][0] += a0 * b.x; acc[0][1] += a0 * b.y;
            acc[0][2] += a0 * b.z; acc[0][3] += a0 * b.w;
            acc[1][0] += a1 * b.x; acc[1][1] += a1 * b.y;
            acc[1][2] += a1 * b.z; acc[1][3] += a1 * b.w;
        }
        __syncthreads();
    }
#pragma unroll
    for (int r = 0; r < 2; ++r) {
        float4 v = make_float4(acc[r][0], acc[r][1], acc[r][2], acc[r][3]);
        *(float4*)&g_h[(size_t)(m0 + ty * 2 + r) * C_TOT + n0 + tx * 4] = v;
    }
}

// ---------------------------------------------------------------------------
// K2: exp tables
// ---------------------------------------------------------------------------
__global__ __launch_bounds__(128) void k_prep(const float* __restrict__ a) {
    const int n    = blockIdx.x;
    const int h    = threadIdx.x >> 5;
    const int lane = threadIdx.x & 31;
    const float* base = g_h + n * C_TOT + h * F_OUT;

    float hv0 = base[lane], hv1 = base[lane + 32];
    float ei = hv0 * a[lane]      + hv1 * a[lane + 32];
    float ej = hv0 * a[64 + lane] + hv1 * a[96 + lane];
#pragma unroll
    for (int off = 16; off; off >>= 1) {
        ei += __shfl_down_sync(0xffffffffu, ei, off);
        ej += __shfl_down_sync(0xffffffffu, ej, off);
    }
    if (lane == 0) {
        int idx = n * HEADS + h;
        g_P1[idx] = expf(ei);
        g_P2[idx] = expf(0.2f * ei);
        g_Q1[idx] = expf(ej);
        g_Q2[idx] = expf(0.2f * ej);
    }
}

// ---------------------------------------------------------------------------
// K3a: pack adjacency to bitmask. int4 loads + shfl-OR word assembly.
// ---------------------------------------------------------------------------
__global__ __launch_bounds__(128) void k_pack(const int* __restrict__ adj) {
    const int i    = blockIdx.x;
    const int w    = threadIdx.x >> 5;
    const int lane = threadIdx.x & 31;
    const size_t rb = (size_t)i * N_NODES;
#pragma unroll
    for (int c = w; c < 32; c += 4) {            // chunk = 128 j
        int4 v = *(const int4*)&adj[rb + c * 128 + lane * 4];
        unsigned n = (v.x != 0 ? 1u : 0u) | (v.y != 0 ? 2u : 0u)
                   | (v.z != 0 ? 4u : 0u) | (v.w != 0 ? 8u : 0u);
        unsigned word = n << (4 * (lane & 7));
        word |= __shfl_xor_sync(0xffffffffu, word, 1);
        word |= __shfl_xor_sync(0xffffffffu, word, 2);
        word |= __shfl_xor_sync(0xffffffffu, word, 4);
        if ((lane & 7) == 0)
            g_adjm[i * NWORDS + c * 4 + (lane >> 3)] = word;
    }
}

// ---------------------------------------------------------------------------
// K3b: mma.sync tf32 aggregation, v4.
//  256 threads = 8 warps x 16 i-rows (128 i/CTA). H tile f-permuted
//  (p = (f&7)*8 + f>>3) + XOR-swizzled granules (q ^ (j&3)) ->
//  4x LDS.128 per k-step, conflict-free. launch_bounds(256,2) for occupancy.
// ---------------------------------------------------------------------------
__device__ __forceinline__ void mma_tf32(float c[4],
                                         unsigned a0, unsigned a1,
                                         unsigned a2, unsigned a3,
                                         unsigned b0, unsigned b1) {
    asm volatile(
        "mma.sync.aligned.m16n8k8.row.col.f32.tf32.tf32.f32 "
        "{%0,%1,%2,%3}, {%4,%5,%6,%7}, {%8,%9}, {%0,%1,%2,%3};"
        : "+f"(c[0]), "+f"(c[1]), "+f"(c[2]), "+f"(c[3])
        : "r"(a0), "r"(a1), "r"(a2), "r"(a3), "r"(b0), "r"(b1));
}
__device__ __forceinline__ unsigned to_tf32(float x) {
    unsigned u;
    asm("cvt.rna.tf32.f32 %0, %1;" : "=r"(u) : "f"(x));
    return u;
}

__global__ __launch_bounds__(256, 2) void k_aggr_v4() {
    __shared__ __align__(16) float  hsP[JTILE * HSTR];   // 18 KB
    __shared__ __align__(8)  float2 qs[JTILE];

    const int t    = threadIdx.x;
    const int w    = t >> 5;
    const int lane = t & 31;
    const int g    = lane >> 2;
    const int tg   = lane & 3;
    const int head = blockIdx.y;
    const int js   = blockIdx.z;
    const int i0   = blockIdx.x * 128 + w * 16 + g;
    const int r0   = i0;
    const int r1   = i0 + 8;

    const float p1a = g_P1[r0 * HEADS + head], p2a = g_P2[r0 * HEADS + head];
    const float p1b = g_P1[r1 * HEADS + head], p2b = g_P2[r1 * HEADS + head];

    float acc[8][4];
#pragma unroll
    for (int nt = 0; nt < 8; ++nt)
#pragma unroll
        for (int k = 0; k < 4; ++k) acc[nt][k] = 0.f;
    float den0 = 0.f, den1 = 0.f;

    const unsigned* am0 = g_adjm + r0 * NWORDS;
    const unsigned* am1 = g_adjm + r1 * NWORDS;

    for (int tile = 0; tile < JPER / JTILE; ++tile) {
        const int j0 = js * JPER + tile * JTILE;

        __syncthreads();
        // ---- stage H tile: f-permuted, XOR-swizzled, tf32-rounded ----
#pragma unroll
        for (int s = 0; s < 4; ++s) {
            int idx = t + s * 256;               // 1024 granules
            int jj = idx >> 4, b4 = idx & 15;
            const float* src = &g_h[(size_t)(j0 + jj) * C_TOT + head * F_OUT
                                    + ((b4 & 1) << 5) + (b4 >> 1)];
            uint4 o;
            o.x = to_tf32(src[0]);
            o.y = to_tf32(src[8]);
            o.z = to_tf32(src[16]);
            o.w = to_tf32(src[24]);
            *(uint4*)&hsP[jj * HSTR + ((b4 ^ (jj & 3)) << 2)] = o;
        }
        if (t < JTILE)
            qs[t] = make_float2(g_Q1[(j0 + t) * HEADS + head],
                                g_Q2[(j0 + t) * HEADS + head]);
        __syncthreads();

        const int wd = j0 >> 5;
        const unsigned m0a = am0[wd], m0b = am0[wd + 1];
        const unsigned m1a = am1[wd], m1b = am1[wd + 1];

#pragma unroll
        for (int kk = 0; kk < 8; ++kk) {
            const int j_lo = kk * 8 + tg;
            const int j_hi = j_lo + 4;
            const int sh   = (kk & 3) * 8;
            const unsigned w0 = (kk < 4) ? m0a : m0b;
            const unsigned w1 = (kk < 4) ? m1a : m1b;

            const float2 qlo = qs[j_lo];
            const float2 qhi = qs[j_hi];

            // B fragments: 4x LDS.128, conflict-free via XOR swizzle
            float bl[8], bh[8];
            const int blo = j_lo * HSTR, bhi = j_hi * HSTR;
            *(float4*)&bl[0] = *(const float4*)&hsP[blo + (((g * 2)     ^ tg) << 2)];
            *(float4*)&bl[4] = *(const float4*)&hsP[blo + (((g * 2 + 1) ^ tg) << 2)];
            *(float4*)&bh[0] = *(const float4*)&hsP[bhi + (((g * 2)     ^ tg) << 2)];
            *(float4*)&bh[4] = *(const float4*)&hsP[bhi + (((g * 2 + 1) ^ tg) << 2)];

            float v00 = fmaxf(p1a * qlo.x, p2a * qlo.y);
            float v10 = fmaxf(p1b * qlo.x, p2b * qlo.y);
            float v01 = fmaxf(p1a * qhi.x, p2a * qhi.y);
            float v11 = fmaxf(p1b * qhi.x, p2b * qhi.y);
            v00 = ((w0 >> (sh + tg))     & 1u) ? v00 : 0.f;
            v10 = ((w1 >> (sh + tg))     & 1u) ? v10 : 0.f;
            v01 = ((w0 >> (sh + tg + 4)) & 1u) ? v01 : 0.f;
            v11 = ((w1 >> (sh + tg + 4)) & 1u) ? v11 : 0.f;

            unsigned ua0 = to_tf32(v00);
            unsigned ua1 = to_tf32(v10);
            unsigned ua2 = to_tf32(v01);
            unsigned ua3 = to_tf32(v11);
            den0 += __uint_as_float(ua0) + __uint_as_float(ua2);
            den1 += __uint_as_float(ua1) + __uint_as_float(ua3);

#pragma unroll
            for (int nt = 0; nt < 8; ++nt)
                mma_tf32(acc[nt], ua0, ua1, ua2, ua3,
                         __float_as_uint(bl[nt]), __float_as_uint(bh[nt]));
        }
    }

    // ---- epilogue ----
    den0 += __shfl_xor_sync(0xffffffffu, den0, 1);
    den0 += __shfl_xor_sync(0xffffffffu, den0, 2);
    den1 += __shfl_xor_sync(0xffffffffu, den1, 1);
    den1 += __shfl_xor_sync(0xffffffffu, den1, 2);

    const size_t pb = (size_t)(js * HEADS + head) * N_NODES;
    if (tg == 0) {
        g_pden[pb + r0] = den0;
        g_pden[pb + r1] = den1;
    }
    float* p0 = &g_part[(pb + r0) * F_OUT];
    float* p1 = &g_part[(pb + r1) * F_OUT];
#pragma unroll
    for (int nt = 0; nt < 8; ++nt) {
        const int f = nt * 8 + tg * 2;
        *(float2*)&p0[f] = make_float2(acc[nt][0], acc[nt][1]);
        *(float2*)&p1[f] = make_float2(acc[nt][2], acc[nt][3]);
    }
}

// ---------------------------------------------------------------------------
// K4: combine partials over j-splits and heads
// ---------------------------------------------------------------------------
__global__ __launch_bounds__(256) void k_combine(float* __restrict__ out) {
    const int t = blockIdx.x * 256 + threadIdx.x;
    const int i = t >> 6;
    const int f = t & 63;
    float v = 0.f;
#pragma unroll
    for (int h = 0; h < HEADS; ++h) {
        float num = 0.f, den = 0.f;
#pragma unroll
        for (int s = 0; s < JSPLIT; ++s) {
            num += g_part[((size_t)(s * HEADS + h) * N_NODES + i) * F_OUT + f];
            den += g_pden[(size_t)(s * HEADS + h) * N_NODES + i];
        }
        v += num / den;
    }
    out[t] = 0.25f * v;
}

// ---------------------------------------------------------------------------
extern "C" void kernel_launch(void* const* d_in, const int* in_sizes, int n_in,
                              void* d_out, int out_size) {
    const float* x   = (const float*)d_in[0];
    const int*   adj = (const int*)  d_in[1];
    const float* W   = (const float*)d_in[2];
    const float* a   = (const float*)d_in[3];
    float* out = (float*)d_out;

    k_gemm<<<dim3(C_TOT / 64, N_NODES / 32), 256>>>(x, W);
    k_prep<<<N_NODES, 128>>>(a);
    k_pack<<<N_NODES, 128>>>(adj);
    k_aggr_v4<<<dim3(N_NODES / 128, HEADS, JSPLIT), 256>>>();
    k_combine<<<(N_NODES * F_OUT) / 256, 256>>>(out);
}